// round 6
// baseline (speedup 1.0000x reference)
#include <cuda_runtime.h>
#include <cstdint>

// ThresholdDecision: out[b] = 1.0f iff indicator (x[b,l,2] > 0.5) has a run of
// 4 consecutive ones ending at l in [4, L-2].
//
// One warp per row. R5 finding: kernel is serial-latency bound (DRAM 4%,
// issue 8.7%) — the tail warp scans ~10 chunks with one DRAM round trip each.
// Fix: batch GROUP=4 chunks (128 positions) per iteration so the 4 loads are
// in flight together (MLP=4), cutting the tail's serial chain ~4x.

#define B_ROWS 4096
#define L_LEN  4096
#define THRESH 0.5f

#define WARPS_PER_BLOCK 8
#define THREADS (WARPS_PER_BLOCK * 32)
#define NBLOCKS (B_ROWS / WARPS_PER_BLOCK)     // 512
#define NCHUNK  (L_LEN / 32)                   // 128
#define GROUP   4                              // chunks per iteration
#define NGROUPS (NCHUNK / GROUP)               // 32

__global__ void threshold_decision_kernel(const float* __restrict__ x,
                                          float* __restrict__ out,
                                          int size_ok) {
    const int row_id = blockIdx.x * WARPS_PER_BLOCK + (threadIdx.x >> 5);
    const int lane   = threadIdx.x & 31;
    const float* row = x + (size_t)row_id * (size_t)(L_LEN * 3);

    unsigned carry = 0;   // indicator bits for positions base-3..base-1
    float result = 0.0f;

    for (int g = 0; g < NGROUPS; ++g) {
        const int base0 = g * (GROUP * 32);

        // Front-batched independent loads: MLP = GROUP
        float v[GROUP];
        #pragma unroll
        for (int k = 0; k < GROUP; ++k)
            v[k] = row[(base0 + k * 32 + lane) * 3 + 2];

        unsigned e_any = 0;
        #pragma unroll
        for (int k = 0; k < GROUP; ++k) {
            const unsigned m = __ballot_sync(0xffffffffu, v[k] > THRESH);

            // m64 bit j corresponds to position base0 + 32k + j - 3
            const uint64_t m64 = ((uint64_t)m << 3) | (uint64_t)carry;
            carry = m >> 29;

            const uint64_t r = m64 & (m64 >> 1) & (m64 >> 2) & (m64 >> 3);
            unsigned e = (unsigned)r;          // bit j: 4-run ends at base0+32k+j

            if (g == 0 && k == 0)
                e &= 0xFFFFFFF0u;              // require run end >= 4
            if (g == NGROUPS - 1 && k == GROUP - 1)
                e &= 0x7FFFFFFFu;              // require run end <= L-2 (4094)

            e_any |= e;
        }

        if (e_any) { result = 1.0f; break; }   // ballot math -> warp-uniform
    }

    if (lane == 0) {
        if (!size_ok) result = 4444.0f;        // diagnostic: bad n_in/in_sizes
        out[row_id] = result;
    }
}

extern "C" void kernel_launch(void* const* d_in, const int* in_sizes, int n_in,
                              void* d_out, int out_size) {
    const float* x = (const float*)d_in[0];
    float* out = (float*)d_out;
    const long long expect = (long long)B_ROWS * L_LEN * 3;
    const int size_ok = (n_in >= 1) && ((long long)in_sizes[0] == expect) &&
                        (out_size == B_ROWS);
    threshold_decision_kernel<<<NBLOCKS, THREADS>>>(x, out, size_ok);
}

// round 7
// speedup vs baseline: 1.1062x; 1.1062x over previous
#include <cuda_runtime.h>
#include <cstdint>

// ThresholdDecision: out[b] = 1.0f iff indicator (x[b,l,2] > 0.5) has a run of
// 4 consecutive ones ending at l in [4, L-2].
//
// One warp per row. R6 finding: duration (~6.8us) tracks burst-service time of
// the first-group loads, not steady-state BW; per-warp serial tail rides on
// latency-inflated round trips. This round: first window = 256 positions
// (GROUP=8, P(miss) ~ 3e-4 -> tail vanishes) + 4 warps/CTA (grid 1024) for
// better per-SM balance of the burst.

#define B_ROWS 4096
#define L_LEN  4096
#define THRESH 0.5f

#define WARPS_PER_BLOCK 4
#define THREADS (WARPS_PER_BLOCK * 32)
#define NBLOCKS (B_ROWS / WARPS_PER_BLOCK)     // 1024
#define NCHUNK  (L_LEN / 32)                   // 128
#define GROUP   8                              // chunks per iteration (256 pos)
#define NGROUPS (NCHUNK / GROUP)               // 16

__global__ __launch_bounds__(THREADS)
void threshold_decision_kernel(const float* __restrict__ x,
                               float* __restrict__ out,
                               int size_ok) {
    const int row_id = blockIdx.x * WARPS_PER_BLOCK + (threadIdx.x >> 5);
    const int lane   = threadIdx.x & 31;
    const float* row = x + (size_t)row_id * (size_t)(L_LEN * 3);

    unsigned carry = 0;   // indicator bits for positions base-3..base-1
    float result = 0.0f;

    for (int g = 0; g < NGROUPS; ++g) {
        const int base0 = g * (GROUP * 32);

        // Front-batched independent loads: MLP = GROUP = 8
        float v[GROUP];
        #pragma unroll
        for (int k = 0; k < GROUP; ++k)
            v[k] = row[(base0 + k * 32 + lane) * 3 + 2];

        unsigned e_any = 0;
        #pragma unroll
        for (int k = 0; k < GROUP; ++k) {
            const unsigned m = __ballot_sync(0xffffffffu, v[k] > THRESH);

            // m64 bit j corresponds to position base0 + 32k + j - 3
            const uint64_t m64 = ((uint64_t)m << 3) | (uint64_t)carry;
            carry = m >> 29;

            const uint64_t r = m64 & (m64 >> 1) & (m64 >> 2) & (m64 >> 3);
            unsigned e = (unsigned)r;          // bit j: 4-run ends at base0+32k+j

            if (g == 0 && k == 0)
                e &= 0xFFFFFFF0u;              // require run end >= 4
            if (g == NGROUPS - 1 && k == GROUP - 1)
                e &= 0x7FFFFFFFu;              // require run end <= L-2 (4094)

            e_any |= e;
        }

        if (e_any) { result = 1.0f; break; }   // ballot math -> warp-uniform
    }

    if (lane == 0) {
        if (!size_ok) result = 4444.0f;        // diagnostic: bad n_in/in_sizes
        out[row_id] = result;
    }
}

extern "C" void kernel_launch(void* const* d_in, const int* in_sizes, int n_in,
                              void* d_out, int out_size) {
    const float* x = (const float*)d_in[0];
    float* out = (float*)d_out;
    const long long expect = (long long)B_ROWS * L_LEN * 3;
    const int size_ok = (n_in >= 1) && ((long long)in_sizes[0] == expect) &&
                        (out_size == B_ROWS);
    threshold_decision_kernel<<<NBLOCKS, THREADS>>>(x, out, size_ok);
}

// round 9
// speedup vs baseline: 1.2019x; 1.0865x over previous
#include <cuda_runtime.h>
#include <cstdint>

// ThresholdDecision: out[b] = 1.0f iff indicator (x[b,l,2] > 0.5) has a run of
// 4 consecutive ones ending at l in [4, L-2].
//
// R7 model: duration ~= fixed overhead + one chip-wide burst-service epoch;
// invariant to traffic (2.4-12.6 MB all ~6.5-7.5us). Optimize the knee:
// GROUP=6 (192-pos first window, P(miss)~0.25% -> ~10 rows take a 2nd trip)
// minimizes burst bytes while keeping the serial tail ~zero. __ldcg skips L1
// allocation for this single-use stream.

#define B_ROWS 4096
#define L_LEN  4096
#define THRESH 0.5f

#define WARPS_PER_BLOCK 4
#define THREADS (WARPS_PER_BLOCK * 32)
#define NBLOCKS (B_ROWS / WARPS_PER_BLOCK)     // 1024
#define GROUP   6                              // chunks per iteration (192 pos)
#define NGROUPS ((L_LEN / 32) / GROUP)         // 21 full groups (4032 pos)
#define TAIL_BASE (NGROUPS * GROUP * 32)       // 4032: last 64 pos handled after

__global__ __launch_bounds__(THREADS)
void threshold_decision_kernel(const float* __restrict__ x,
                               float* __restrict__ out,
                               int size_ok) {
    const int row_id = blockIdx.x * WARPS_PER_BLOCK + (threadIdx.x >> 5);
    const int lane   = threadIdx.x & 31;
    const float* row = x + (size_t)row_id * (size_t)(L_LEN * 3);

    unsigned carry = 0;   // indicator bits for positions base-3..base-1
    float result = 0.0f;
    bool done = false;

    for (int g = 0; g < NGROUPS; ++g) {
        const int base0 = g * (GROUP * 32);

        // Front-batched independent L2-only loads: MLP = GROUP = 6
        float v[GROUP];
        #pragma unroll
        for (int k = 0; k < GROUP; ++k)
            v[k] = __ldcg(&row[(base0 + k * 32 + lane) * 3 + 2]);

        unsigned e_any = 0;
        #pragma unroll
        for (int k = 0; k < GROUP; ++k) {
            const unsigned m = __ballot_sync(0xffffffffu, v[k] > THRESH);

            // m64 bit j corresponds to position base0 + 32k + j - 3
            const uint64_t m64 = ((uint64_t)m << 3) | (uint64_t)carry;
            carry = m >> 29;

            const uint64_t r = m64 & (m64 >> 1) & (m64 >> 2) & (m64 >> 3);
            unsigned e = (unsigned)r;          // bit j: 4-run ends at base0+32k+j

            if (g == 0 && k == 0)
                e &= 0xFFFFFFF0u;              // require run end >= 4

            e_any |= e;
        }

        if (e_any) { result = 1.0f; done = true; break; }  // warp-uniform
    }

    // Remaining 64 positions (4032..4095); run end must be <= L-2 (4094).
    if (!done) {
        #pragma unroll
        for (int k = 0; k < 2; ++k) {
            const int base = TAIL_BASE + k * 32;
            const float v = __ldcg(&row[(base + lane) * 3 + 2]);
            const unsigned m = __ballot_sync(0xffffffffu, v > THRESH);
            const uint64_t m64 = ((uint64_t)m << 3) | (uint64_t)carry;
            carry = m >> 29;
            const uint64_t r = m64 & (m64 >> 1) & (m64 >> 2) & (m64 >> 3);
            unsigned e = (unsigned)r;
            if (k == 1) e &= 0x7FFFFFFFu;      // exclude run end at L-1
            if (e) result = 1.0f;
        }
    }

    if (lane == 0) {
        if (!size_ok) result = 4444.0f;        // diagnostic: bad n_in/in_sizes
        out[row_id] = result;
    }
}

extern "C" void kernel_launch(void* const* d_in, const int* in_sizes, int n_in,
                              void* d_out, int out_size) {
    const float* x = (const float*)d_in[0];
    float* out = (float*)d_out;
    const long long expect = (long long)B_ROWS * L_LEN * 3;
    const int size_ok = (n_in >= 1) && ((long long)in_sizes[0] == expect) &&
                        (out_size == B_ROWS);
    threshold_decision_kernel<<<NBLOCKS, THREADS>>>(x, out, size_ok);
}